// round 12
// baseline (speedup 1.0000x reference)
#include <cuda_runtime.h>
#include <cuda_bf16.h>
#include <cstdint>
#include <cstddef>

// ---------------------------------------------------------------------------
// QNetwork: GRU cell + 2-layer MLP head, B=65536
//   sa = [state|action]  (B,320)
//   gi = sa @ w_ih^T     (B,1536)
//   gh = h  @ w_hh^T     (B,1536)
//   r = sig(i_r+h_r+b), z = sig(i_z+h_z+b), n = tanh(i_n+b + r*(h_n+b))
//   h_new = (1-z)*n + z*h
//   x1 = relu(h_new@w1^T+b1); x2 = relu(x1@w2^T+b2); q = x2@w3^T+b3
// Outputs (flattened tuple concat): q (65536 floats) then h_new (65536*512).
// ---------------------------------------------------------------------------

#define BATCH   65536
#define SDIM    256
#define ADIM    64
#define INDIM   320
#define GDIM    512
#define HDIM    1024
#define G3      1536

// Scratch (no cudaMalloc allowed -> __device__ globals)
__device__ float g_sa[(size_t)BATCH * INDIM];
__device__ float g_gi[(size_t)BATCH * G3];
__device__ float g_gh[(size_t)BATCH * G3];
__device__ float g_x1[(size_t)BATCH * HDIM];
__device__ float g_x2[(size_t)BATCH * HDIM];

// ---------------- f32x2 packed-FMA helpers (FFMA2 path, sm_103a) ----------
__device__ __forceinline__ unsigned long long pk2(float lo, float hi) {
    unsigned long long r;
    asm("mov.b64 %0, {%1, %2};"
        : "=l"(r) : "r"(__float_as_uint(lo)), "r"(__float_as_uint(hi)));
    return r;
}
__device__ __forceinline__ void upk2(unsigned long long v, float& lo, float& hi) {
    unsigned int a, b;
    asm("mov.b64 {%0, %1}, %2;" : "=r"(a), "=r"(b) : "l"(v));
    lo = __uint_as_float(a);
    hi = __uint_as_float(b);
}
__device__ __forceinline__ void fma2(unsigned long long& d,
                                     unsigned long long a,
                                     unsigned long long b) {
    asm("fma.rn.f32x2 %0, %1, %2, %0;" : "+l"(d) : "l"(a), "l"(b));
}

// ---------------------------------------------------------------------------
// SGEMM (NT): C[M,N] = A[M,K] @ W[N,K]^T (+bias, +relu)
// BM=BN=128, BK=8, 256 threads, 8x8 microtile, double-buffered smem,
// inner product via packed f32x2 FMA (2 MACs / instr).
// Requires: M%128==0, N%128==0, K%8==0.
// ---------------------------------------------------------------------------
template <bool BIAS, bool RELU>
__global__ __launch_bounds__(256, 2)
void sgemm_nt(const float* __restrict__ A, const float* __restrict__ W,
              const float* __restrict__ bias, float* __restrict__ C,
              int M, int N, int K)
{
    __shared__ float As[2][8][132];
    __shared__ float Bs[2][8][132];

    const int tid = threadIdx.x;
    const int m0  = blockIdx.y * 128;
    const int n0  = blockIdx.x * 128;

    // gmem staging: each thread loads one float4 of A and one of W per tile
    const int ldRow = tid >> 1;          // 0..127
    const int ldCol = (tid & 1) * 4;     // 0 or 4

    const float* Aptr = A + (size_t)(m0 + ldRow) * K + ldCol;
    const float* Wptr = W + (size_t)(n0 + ldRow) * K + ldCol;

    const int tm = (tid >> 4) * 4;       // 0..60
    const int tn = (tid & 15) * 4;       // 0..60

    unsigned long long acc[8][4];
#pragma unroll
    for (int i = 0; i < 8; ++i)
#pragma unroll
        for (int j = 0; j < 4; ++j) acc[i][j] = 0ULL;

    const int numTiles = K >> 3;

    // prologue: load tile 0 into buffer 0
    float4 aReg = *(const float4*)Aptr;
    float4 wReg = *(const float4*)Wptr;
    As[0][ldCol + 0][ldRow] = aReg.x; As[0][ldCol + 1][ldRow] = aReg.y;
    As[0][ldCol + 2][ldRow] = aReg.z; As[0][ldCol + 3][ldRow] = aReg.w;
    Bs[0][ldCol + 0][ldRow] = wReg.x; Bs[0][ldCol + 1][ldRow] = wReg.y;
    Bs[0][ldCol + 2][ldRow] = wReg.z; Bs[0][ldCol + 3][ldRow] = wReg.w;
    __syncthreads();

    for (int t = 0; t < numTiles; ++t) {
        const int buf = t & 1;
        if (t + 1 < numTiles) {
            aReg = *(const float4*)(Aptr + (size_t)(t + 1) * 8);
            wReg = *(const float4*)(Wptr + (size_t)(t + 1) * 8);
        }
#pragma unroll
        for (int kk = 0; kk < 8; ++kk) {
            const float4 a0 = *(const float4*)&As[buf][kk][tm];
            const float4 a1 = *(const float4*)&As[buf][kk][64 + tm];
            const float4 b0 = *(const float4*)&Bs[buf][kk][tn];
            const float4 b1 = *(const float4*)&Bs[buf][kk][64 + tn];
            unsigned long long bp[4];
            bp[0] = pk2(b0.x, b0.y); bp[1] = pk2(b0.z, b0.w);
            bp[2] = pk2(b1.x, b1.y); bp[3] = pk2(b1.z, b1.w);
            const float av[8] = {a0.x, a0.y, a0.z, a0.w, a1.x, a1.y, a1.z, a1.w};
#pragma unroll
            for (int i = 0; i < 8; ++i) {
                const unsigned long long ap = pk2(av[i], av[i]);
#pragma unroll
                for (int j = 0; j < 4; ++j) fma2(acc[i][j], ap, bp[j]);
            }
        }
        if (t + 1 < numTiles) {
            const int nb = buf ^ 1;
            As[nb][ldCol + 0][ldRow] = aReg.x; As[nb][ldCol + 1][ldRow] = aReg.y;
            As[nb][ldCol + 2][ldRow] = aReg.z; As[nb][ldCol + 3][ldRow] = aReg.w;
            Bs[nb][ldCol + 0][ldRow] = wReg.x; Bs[nb][ldCol + 1][ldRow] = wReg.y;
            Bs[nb][ldCol + 2][ldRow] = wReg.z; Bs[nb][ldCol + 3][ldRow] = wReg.w;
            __syncthreads();
        }
    }

    // epilogue
    float4 bb0 = make_float4(0.f, 0.f, 0.f, 0.f);
    float4 bb1 = make_float4(0.f, 0.f, 0.f, 0.f);
    if (BIAS) {
        bb0 = *(const float4*)&bias[n0 + tn];
        bb1 = *(const float4*)&bias[n0 + 64 + tn];
    }
#pragma unroll
    for (int i = 0; i < 8; ++i) {
        const int row = m0 + ((i < 4) ? (tm + i) : (64 + tm + (i - 4)));
        float c0, c1, c2, c3, c4, c5, c6, c7;
        upk2(acc[i][0], c0, c1); upk2(acc[i][1], c2, c3);
        upk2(acc[i][2], c4, c5); upk2(acc[i][3], c6, c7);
        if (BIAS) {
            c0 += bb0.x; c1 += bb0.y; c2 += bb0.z; c3 += bb0.w;
            c4 += bb1.x; c5 += bb1.y; c6 += bb1.z; c7 += bb1.w;
        }
        if (RELU) {
            c0 = fmaxf(c0, 0.f); c1 = fmaxf(c1, 0.f);
            c2 = fmaxf(c2, 0.f); c3 = fmaxf(c3, 0.f);
            c4 = fmaxf(c4, 0.f); c5 = fmaxf(c5, 0.f);
            c6 = fmaxf(c6, 0.f); c7 = fmaxf(c7, 0.f);
        }
        float* crow = C + (size_t)row * N;
        *(float4*)&crow[n0 + tn]      = make_float4(c0, c1, c2, c3);
        *(float4*)&crow[n0 + 64 + tn] = make_float4(c4, c5, c6, c7);
    }
}

// ---------------------------------------------------------------------------
// Pack sa = [state | action]  -> (B, 320)
// ---------------------------------------------------------------------------
__global__ void pack_sa_kernel(const float4* __restrict__ st,
                               const float4* __restrict__ ac,
                               float4* __restrict__ sa)
{
    const int idx = blockIdx.x * blockDim.x + threadIdx.x;   // over B*80 float4s
    if (idx >= BATCH * (INDIM / 4)) return;
    const int row = idx / 80;
    const int c   = idx - row * 80;
    sa[idx] = (c < 64) ? st[(size_t)row * 64 + c] : ac[(size_t)row * 16 + (c - 64)];
}

// ---------------------------------------------------------------------------
// GRU pointwise: consumes gi, gh, h, biases -> h_new (float4-vectorized)
// ---------------------------------------------------------------------------
__device__ __forceinline__ float sigm(float x) { return 1.f / (1.f + expf(-x)); }

__global__ void gru_pointwise(const float* __restrict__ gi,
                              const float* __restrict__ gh,
                              const float* __restrict__ h,
                              const float* __restrict__ b_ih,
                              const float* __restrict__ b_hh,
                              float* __restrict__ hnew)
{
    const int idx = blockIdx.x * blockDim.x + threadIdx.x;   // over B*128 float4s
    if (idx >= BATCH * (GDIM / 4)) return;
    const int b = idx >> 7;
    const int j = (idx & 127) << 2;
    const size_t gbase = (size_t)b * G3 + j;

    const float4 ir = *(const float4*)(gi + gbase);
    const float4 iz = *(const float4*)(gi + gbase + GDIM);
    const float4 in = *(const float4*)(gi + gbase + 2 * GDIM);
    const float4 hr = *(const float4*)(gh + gbase);
    const float4 hz = *(const float4*)(gh + gbase + GDIM);
    const float4 hn = *(const float4*)(gh + gbase + 2 * GDIM);

    const float4 bir = *(const float4*)(b_ih + j);
    const float4 biz = *(const float4*)(b_ih + GDIM + j);
    const float4 bin = *(const float4*)(b_ih + 2 * GDIM + j);
    const float4 bhr = *(const float4*)(b_hh + j);
    const float4 bhz = *(const float4*)(b_hh + GDIM + j);
    const float4 bhn = *(const float4*)(b_hh + 2 * GDIM + j);

    const float4 hp = *(const float4*)(h + (size_t)b * GDIM + j);

    float4 out;
    {
        const float r = sigm(ir.x + bir.x + hr.x + bhr.x);
        const float z = sigm(iz.x + biz.x + hz.x + bhz.x);
        const float n = tanhf(in.x + bin.x + r * (hn.x + bhn.x));
        out.x = (1.f - z) * n + z * hp.x;
    }
    {
        const float r = sigm(ir.y + bir.y + hr.y + bhr.y);
        const float z = sigm(iz.y + biz.y + hz.y + bhz.y);
        const float n = tanhf(in.y + bin.y + r * (hn.y + bhn.y));
        out.y = (1.f - z) * n + z * hp.y;
    }
    {
        const float r = sigm(ir.z + bir.z + hr.z + bhr.z);
        const float z = sigm(iz.z + biz.z + hz.z + bhz.z);
        const float n = tanhf(in.z + bin.z + r * (hn.z + bhn.z));
        out.z = (1.f - z) * n + z * hp.z;
    }
    {
        const float r = sigm(ir.w + bir.w + hr.w + bhr.w);
        const float z = sigm(iz.w + biz.w + hz.w + bhz.w);
        const float n = tanhf(in.w + bin.w + r * (hn.w + bhn.w));
        out.w = (1.f - z) * n + z * hp.w;
    }
    *(float4*)(hnew + (size_t)b * GDIM + j) = out;
}

// ---------------------------------------------------------------------------
// q = x2 @ w3^T + b3  (one warp per batch row)
// ---------------------------------------------------------------------------
__global__ void gemv_q(const float* __restrict__ x2, const float* __restrict__ w3,
                       const float* __restrict__ b3, float* __restrict__ q)
{
    const int warp = (blockIdx.x * blockDim.x + threadIdx.x) >> 5;
    const int lane = threadIdx.x & 31;
    if (warp >= BATCH) return;
    const float4* xr = (const float4*)(x2 + (size_t)warp * HDIM);
    const float4* w4 = (const float4*)w3;
    float s = 0.f;
#pragma unroll
    for (int i = 0; i < 8; ++i) {
        const float4 a = xr[lane + 32 * i];
        const float4 b = __ldg(&w4[lane + 32 * i]);
        s += a.x * b.x + a.y * b.y + a.z * b.z + a.w * b.w;
    }
#pragma unroll
    for (int o = 16; o; o >>= 1) s += __shfl_xor_sync(0xffffffffu, s, o);
    if (lane == 0) q[warp] = s + __ldg(b3);
}

// ---------------------------------------------------------------------------
extern "C" void kernel_launch(void* const* d_in, const int* in_sizes, int n_in,
                              void* d_out, int out_size)
{
    const float* state  = (const float*)d_in[0];
    const float* action = (const float*)d_in[1];
    const float* hidden = (const float*)d_in[2];   // (1,B,G) == (B,G)
    const float* w_ih   = (const float*)d_in[3];   // (1536,320)
    const float* w_hh   = (const float*)d_in[4];   // (1536,512)
    const float* b_ih   = (const float*)d_in[5];
    const float* b_hh   = (const float*)d_in[6];
    const float* w1     = (const float*)d_in[7];   // (1024,512)
    const float* b1     = (const float*)d_in[8];
    const float* w2     = (const float*)d_in[9];   // (1024,1024)
    const float* b2     = (const float*)d_in[10];
    const float* w3     = (const float*)d_in[11];  // (1,1024)
    const float* b3     = (const float*)d_in[12];

    float* q    = (float*)d_out;                   // first 65536 floats
    float* hnew = (float*)d_out + BATCH;           // then B*512 floats

    float *sa, *gi, *gh, *x1, *x2;
    cudaGetSymbolAddress((void**)&sa, g_sa);
    cudaGetSymbolAddress((void**)&gi, g_gi);
    cudaGetSymbolAddress((void**)&gh, g_gh);
    cudaGetSymbolAddress((void**)&x1, g_x1);
    cudaGetSymbolAddress((void**)&x2, g_x2);

    // 1) pack [state|action]
    {
        const int n = BATCH * (INDIM / 4);
        pack_sa_kernel<<<(n + 255) / 256, 256>>>((const float4*)state,
                                                 (const float4*)action,
                                                 (float4*)sa);
    }
    // 2) gi = sa @ w_ih^T      (B,1536) K=320
    sgemm_nt<false, false><<<dim3(G3 / 128, BATCH / 128), 256>>>(
        sa, w_ih, nullptr, gi, BATCH, G3, INDIM);
    // 3) gh = h @ w_hh^T       (B,1536) K=512
    sgemm_nt<false, false><<<dim3(G3 / 128, BATCH / 128), 256>>>(
        hidden, w_hh, nullptr, gh, BATCH, G3, GDIM);
    // 4) GRU gates -> h_new (written straight into d_out region)
    {
        const int n = BATCH * (GDIM / 4);
        gru_pointwise<<<(n + 255) / 256, 256>>>(gi, gh, hidden, b_ih, b_hh, hnew);
    }
    // 5) x1 = relu(h_new @ w1^T + b1)   (B,1024) K=512
    sgemm_nt<true, true><<<dim3(HDIM / 128, BATCH / 128), 256>>>(
        hnew, w1, b1, x1, BATCH, HDIM, GDIM);
    // 6) x2 = relu(x1 @ w2^T + b2)      (B,1024) K=1024
    sgemm_nt<true, true><<<dim3(HDIM / 128, BATCH / 128), 256>>>(
        x1, w2, b2, x2, BATCH, HDIM, HDIM);
    // 7) q = x2 @ w3^T + b3
    gemv_q<<<BATCH / 8, 256>>>(x2, w3, b3, q);
}